// round 4
// baseline (speedup 1.0000x reference)
#include <cuda_runtime.h>
#include <math.h>

#define Hh   64
#define Ww   192
#define HW   12288
#define Wp   194
#define Pp   12804      // (64+2)*(192+2)
#define CIN  256
#define COUT 128
#define NPB  192        // p-blocks in gemm grid.x (HW/64)
#define LEAK 0.01f
#define EPSV 1e-5f

// ---------------- scratch (device globals) ----------------------------------
__device__ float g_xpT[Pp * CIN];     // padded input, channel-last [Pp][CIN]
__device__ float g_roT[9 * CIN];      // range_out transposed [9][CIN]
__device__ float g_YT[HW * CIN];      // gather output, channel-last [HW][CIN]
__device__ float g_Z[COUT * HW];      // pre-BN linear outputs
__device__ float g_T[COUT * HW];      // depthwise outputs
__device__ float g_ps[COUT * NPB];    // partial sums per (channel, p-block)
__device__ float g_pq[COUT * NPB];    // partial sum-of-squares
__device__ float g_sc[COUT];          // BN scale
__device__ float g_sh[COUT];          // BN shift

#define FFMA2(d, a, b) asm("fma.rn.f32x2 %0, %1, %2, %0;" : "+l"(d) : "l"(a), "l"(b))

// ---------------- transpose x -> xpT interior --------------------------------
// grid (HW/32=384, CIN/32=8), block (32,8)
__global__ void k_tr(const float* __restrict__ x) {
    __shared__ float t[32][33];
    int p0 = blockIdx.x * 32, c0 = blockIdx.y * 32;
#pragma unroll
    for (int i = threadIdx.y; i < 32; i += 8)
        t[i][threadIdx.x] = x[(c0 + i) * HW + p0 + threadIdx.x];   // t[c][p]
    __syncthreads();
#pragma unroll
    for (int i = threadIdx.y; i < 32; i += 8) {
        int p = p0 + i;
        int r = p / Ww, q = p - r * Ww;
        int pp = (r + 1) * Wp + q + 1;
        g_xpT[pp * CIN + c0 + threadIdx.x] = t[threadIdx.x][i];
    }
}

// zero the pad border rows/cols of xpT. grid 516, block 64 (64*4 floats = 256 ch)
__global__ void k_zb() {
    int b = blockIdx.x, t = threadIdx.x;
    int pp;
    if (b < 194)      pp = b;                       // top row
    else if (b < 388) pp = 65 * Wp + (b - 194);     // bottom row
    else if (b < 452) pp = (b - 388 + 1) * Wp;      // left col rows 1..64
    else              pp = (b - 452 + 1) * Wp + 193;// right col
    *(float4*)(g_xpT + pp * CIN + t * 4) = make_float4(0.f, 0.f, 0.f, 0.f);
}

// transpose range_out (CIN x 9) -> roT (9 x CIN). grid 9, block 256
__global__ void k_rot(const float* __restrict__ ro) {
    g_roT[blockIdx.x * CIN + threadIdx.x] = ro[threadIdx.x * 9 + blockIdx.x];
}

// ---------------- stage-1 deformable gather (channel-last, vectorized) ------
// grid (HW/128=96, CIN/32=8), block (128,2). Thread: 1 pixel, 16 channels.
__global__ __launch_bounds__(256) void k_gather(const float* __restrict__ xr) {
    __shared__ float sro[9][32];
    int tx = threadIdx.x, ty = threadIdx.y;
    int tid = ty * 128 + tx;
    int cb = blockIdx.y * 32;
    for (int i = tid; i < 288; i += 256)                 // FIX: cover all 288
        sro[i / 32][i % 32] = g_roT[(i / 32) * CIN + cb + (i % 32)];
    __syncthreads();

    int p = blockIdx.x * 128 + tx;
    int r = p / Ww, q = p - r * Ww;
    float v = (float)((r + 1) * Wp + (q + 1));
    float o = 3.f / (1.f + expf(-xr[p]));
    int c0 = cb + ty * 16;

    float4 acc[4];
#pragma unroll
    for (int j = 0; j < 4; j++) acc[j] = make_float4(0.f, 0.f, 0.f, 0.f);

    const float PM1 = (float)(Pp - 1);
#pragma unroll
    for (int k = 0; k < 9; k++) {
        float xo = (float)(k % 3 - 1);
        float d  = (float)((k / 3 - 1) * Wp);
        float pre   = v + xo + d;
        float offv  = __fadd_rn(__fmul_rn(o, xo), d);   // mul then add, no FMA
        float after = pre + offv;
        float fo = floorf(offv), co = ceilf(offv);
        float avf  = fminf(fmaxf(pre + fo, 0.f), PM1);
        float avf1 = fminf(fmaxf(avf + xo, 0.f), PM1);
        float avc  = fminf(fmaxf(pre + co, 0.f), PM1);
        float avc1 = fminf(fmaxf(avc + xo, 0.f), PM1);
        float a1 = fabsf((after - avf)  / (float)Wp);
        float a2 = fabsf((avc1 - after) / (float)Wp);
        float w0 = a1 * fabsf(after - avf);
        float w1 = a1 * fabsf(avf1 - after);
        float w2 = a2 * fabsf(avc - after);
        float w3 = a2 * fabsf(after - avc1);
        const float* b0 = g_xpT + (int)avf  * CIN + c0;
        const float* b1 = g_xpT + (int)avf1 * CIN + c0;
        const float* b2 = g_xpT + (int)avc  * CIN + c0;
        const float* b3 = g_xpT + (int)avc1 * CIN + c0;
#pragma unroll
        for (int j = 0; j < 4; j++) {
            float4 vf  = *(const float4*)(b0 + j * 4);
            float4 vf1 = *(const float4*)(b1 + j * 4);
            float4 vc  = *(const float4*)(b2 + j * 4);
            float4 vc1 = *(const float4*)(b3 + j * 4);
            float4 ro4 = *(const float4*)&sro[k][ty * 16 + j * 4];
            float sx = w0 * vf.x + w1 * vf1.x + w2 * vc.x + w3 * vc1.x;
            float sy = w0 * vf.y + w1 * vf1.y + w2 * vc.y + w3 * vc1.y;
            float sz = w0 * vf.z + w1 * vf1.z + w2 * vc.z + w3 * vc1.z;
            float sw = w0 * vf.w + w1 * vf1.w + w2 * vc.w + w3 * vc1.w;
            acc[j].x += ro4.x * sx;
            acc[j].y += ro4.y * sy;
            acc[j].z += ro4.z * sz;
            acc[j].w += ro4.w * sw;
        }
    }
#pragma unroll
    for (int j = 0; j < 4; j++)
        *(float4*)(g_YT + p * CIN + c0 + j * 4) = acc[j];
}

// ---------------- f32x2 GEMM: Z[o,p] = sum_k A[o,k]*B ------------------------
// tile 64o x 64p, 128 threads, microtile 8o x 4p, FFMA2 inner loop.
// BT=true: B is [P][K] (k-contiguous, NT); BT=false: B is [K][HW] (NN).
// Epilogue: writes Z and per-(channel, p-block) partial sum / sumsq.
template <bool BT>
__global__ __launch_bounds__(128) void k_gemm(const float* __restrict__ A,
                                              const float* __restrict__ B,
                                              float* __restrict__ Z, int K) {
    __shared__ float2 As2[16][64];
    __shared__ float  Bs[16][64];
    int bx = blockIdx.x, by = blockIdx.y;
    int pbase = bx * 64, obase = by * 64;
    int tid = threadIdx.x;
    int og = tid >> 4, pg = tid & 15;
    unsigned long long acc[8][2] = {};

    for (int kc = 0; kc < K; kc += 16) {
#pragma unroll
        for (int i = 0; i < 2; i++) {
            int quad = tid + i * 128;
            int oo = quad >> 2, kq = (quad & 3) * 4;
            float4 a = *(const float4*)(A + (obase + oo) * K + kc + kq);
            As2[kq + 0][oo] = make_float2(a.x, a.x);
            As2[kq + 1][oo] = make_float2(a.y, a.y);
            As2[kq + 2][oo] = make_float2(a.z, a.z);
            As2[kq + 3][oo] = make_float2(a.w, a.w);
        }
#pragma unroll
        for (int i = 0; i < 2; i++) {
            int quad = tid + i * 128;
            if (BT) {
                int pp = quad >> 2, kq = (quad & 3) * 4;
                float4 b = *(const float4*)(B + (size_t)(pbase + pp) * K + kc + kq);
                Bs[kq + 0][pp] = b.x; Bs[kq + 1][pp] = b.y;
                Bs[kq + 2][pp] = b.z; Bs[kq + 3][pp] = b.w;
            } else {
                int kk = quad >> 4, pq = (quad & 15) * 4;
                *(float4*)&Bs[kk][pq] =
                    *(const float4*)(B + (size_t)(kc + kk) * HW + pbase + pq);
            }
        }
        __syncthreads();
#pragma unroll
        for (int kk = 0; kk < 16; kk++) {
            ulonglong2 b2 = *(const ulonglong2*)&Bs[kk][pg * 4];
#pragma unroll
            for (int i2 = 0; i2 < 4; i2++) {
                ulonglong2 a2 = *(const ulonglong2*)&As2[kk][og * 8 + i2 * 2];
                FFMA2(acc[i2 * 2 + 0][0], a2.x, b2.x);
                FFMA2(acc[i2 * 2 + 0][1], a2.x, b2.y);
                FFMA2(acc[i2 * 2 + 1][0], a2.y, b2.x);
                FFMA2(acc[i2 * 2 + 1][1], a2.y, b2.y);
            }
        }
        __syncthreads();
    }

    float s[8], qq[8];
#pragma unroll
    for (int i = 0; i < 8; i++) {
        float2 lo = *(float2*)&acc[i][0];
        float2 hi = *(float2*)&acc[i][1];
        *(float4*)(Z + (size_t)(obase + og * 8 + i) * HW + pbase + pg * 4) =
            make_float4(lo.x, lo.y, hi.x, hi.y);
        s[i]  = lo.x + lo.y + hi.x + hi.y;
        qq[i] = lo.x * lo.x + lo.y * lo.y + hi.x * hi.x + hi.y * hi.y;
    }
#pragma unroll
    for (int i = 0; i < 8; i++) {
#pragma unroll
        for (int w = 8; w; w >>= 1) {
            s[i]  += __shfl_down_sync(0xffffffff, s[i],  w, 16);
            qq[i] += __shfl_down_sync(0xffffffff, qq[i], w, 16);
        }
    }
    if (pg == 0) {
#pragma unroll
        for (int i = 0; i < 8; i++) {
            g_ps[(obase + og * 8 + i) * NPB + bx] = s[i];
            g_pq[(obase + og * 8 + i) * NPB + bx] = qq[i];
        }
    }
}

// ---------------- finish BN stats -> scale/shift -----------------------------
__global__ void k_stats2(const float* __restrict__ g, const float* __restrict__ b) {
    __shared__ float ss[256], sq[256];
    int c = blockIdx.x, t = threadIdx.x;
    float s = 0.f, q = 0.f;
    if (t < NPB) { s = g_ps[c * NPB + t]; q = g_pq[c * NPB + t]; }
    ss[t] = s; sq[t] = q;
    __syncthreads();
    for (int st = 128; st; st >>= 1) {
        if (t < st) { ss[t] += ss[t + st]; sq[t] += sq[t + st]; }
        __syncthreads();
    }
    if (t == 0) {
        float mu  = ss[0] / (float)HW;
        float var = sq[0] / (float)HW - mu * mu;
        float rs  = rsqrtf(var + EPSV);
        float sc  = g[c] * rs;
        g_sc[c] = sc;
        g_sh[c] = b[c] - mu * sc;
    }
}

// ---------------- depthwise 3x3 on act(Z) -----------------------------------
__global__ void k_dw(const float* __restrict__ Z, const float* __restrict__ dwz,
                     float* __restrict__ T) {
    int c = blockIdx.y;
    int p = blockIdx.x * 256 + threadIdx.x;
    int r = p / Ww, q = p - r * Ww;
    float sc = g_sc[c], sh = g_sh[c];
    const float* z = Z + (size_t)c * HW;
    float acc = 0.f;
#pragma unroll
    for (int ky = 0; ky < 3; ky++) {
#pragma unroll
        for (int kx = 0; kx < 3; kx++) {
            int rr = r + ky - 1, qc = q + kx - 1;
            if (rr >= 0 && rr < Hh && qc >= 0 && qc < Ww) {
                float v = z[rr * Ww + qc] * sc + sh;
                v = (v >= 0.f) ? v : LEAK * v;
                acc += dwz[c * 9 + ky * 3 + kx] * v;
            }
        }
    }
    T[(size_t)c * HW + p] = acc;
}

// ---------------- final BN+leaky apply ---------------------------------------
__global__ void k_apply(const float* __restrict__ Z, float* __restrict__ out) {
    int i = blockIdx.x * 256 + threadIdx.x;
    int c = i / HW;
    float v = Z[i] * g_sc[c] + g_sh[c];
    out[i] = (v >= 0.f) ? v : LEAK * v;
}

// ---------------- launch ------------------------------------------------------
extern "C" void kernel_launch(void* const* d_in, const int* in_sizes, int n_in,
                              void* d_out, int out_size) {
    const float* x   = (const float*)d_in[0];
    const float* xr  = (const float*)d_in[1];
    const float* ro  = (const float*)d_in[2];
    const float* wr  = (const float*)d_in[3];
    const float* gr  = (const float*)d_in[4];
    const float* br  = (const float*)d_in[5];
    const float* dw1 = (const float*)d_in[6];
    const float* pw1 = (const float*)d_in[7];
    const float* g1  = (const float*)d_in[8];
    const float* b1  = (const float*)d_in[9];
    const float* dw2 = (const float*)d_in[10];
    const float* pw2 = (const float*)d_in[11];
    const float* g2  = (const float*)d_in[12];
    const float* b2  = (const float*)d_in[13];
    float* out = (float*)d_out;

    float *pYT, *pZ, *pT;
    cudaGetSymbolAddress((void**)&pYT, g_YT);
    cudaGetSymbolAddress((void**)&pZ,  g_Z);
    cudaGetSymbolAddress((void**)&pT,  g_T);

    k_tr  <<<dim3(HW / 32, CIN / 32), dim3(32, 8)>>>(x);
    k_zb  <<<516, 64>>>();
    k_rot <<<9, 256>>>(ro);
    k_gather<<<dim3(HW / 128, CIN / 32), dim3(128, 2)>>>(xr);

    k_gemm<true> <<<dim3(NPB, 2), 128>>>(wr, pYT, pZ, CIN);
    k_stats2<<<COUT, 256>>>(gr, br);

    k_dw<<<dim3(HW / 256, COUT), 256>>>(pZ, dw1, pT);
    k_gemm<false><<<dim3(NPB, 2), 128>>>(pw1, pT, pZ, COUT);
    k_stats2<<<COUT, 256>>>(g1, b1);

    k_dw<<<dim3(HW / 256, COUT), 256>>>(pZ, dw2, pT);
    k_gemm<false><<<dim3(NPB, 2), 128>>>(pw2, pT, pZ, COUT);
    k_stats2<<<COUT, 256>>>(g2, b2);

    k_apply<<<(COUT * HW) / 256, 256>>>(pZ, out);
}

// round 5
// speedup vs baseline: 2.5054x; 2.5054x over previous
#include <cuda_runtime.h>
#include <math.h>

#define Hh   64
#define Ww   192
#define HW   12288
#define Wp   194
#define Pp   12804      // (64+2)*(192+2)
#define CIN  256
#define COUT 128
#define NPB  192        // p-blocks in gemm grid.x (HW/64)
#define LEAK 0.01f
#define EPSV 1e-5f

// ---------------- scratch (device globals) ----------------------------------
__device__ float g_xpad[CIN * Pp];    // padded input, channel-major [C][Pp]
__device__ float g_Y[CIN * HW];       // gather output [C][HW]
__device__ float g_Z[COUT * HW];      // pre-BN linear outputs
__device__ float g_T[COUT * HW];      // depthwise outputs
__device__ float g_ps[COUT * NPB];    // partial sums per (channel, p-block)
__device__ float g_pq[COUT * NPB];    // partial sum-of-squares
__device__ float g_sc[COUT];          // BN scale
__device__ float g_sh[COUT];          // BN shift

#define FFMA2(d, a, b) asm("fma.rn.f32x2 %0, %1, %2, %0;" : "+l"(d) : "l"(a), "l"(b))

// ---------------- pad (channel-major) ----------------------------------------
__global__ void k_pad(const float* __restrict__ x) {
    int i = blockIdx.x * 256 + threadIdx.x;
    if (i >= CIN * Pp) return;
    int c = i / Pp, pp = i - c * Pp;
    int pr = pp / Wp, pc = pp - pr * Wp;
    float v = 0.f;
    if (pr >= 1 && pr <= Hh && pc >= 1 && pc <= Ww)
        v = x[c * HW + (pr - 1) * Ww + (pc - 1)];
    g_xpad[i] = v;
}

// ---------------- stage-1 deformable gather ----------------------------------
// grid (HW/128=96, CIN/8=32), block 128. Thread: 1 pixel, 8 channels.
// Fast path (interior rows, no clamp): center taps are exactly zero; side taps
// merge 4 gathers into 3 consecutive loads. Edge blocks use the generic path.
__global__ __launch_bounds__(128) void k_gather(const float* __restrict__ xr,
                                                const float* __restrict__ ro) {
    __shared__ float sro[8][9];
    int tid = threadIdx.x;
    int cb = blockIdx.y * 8;
    if (tid < 72) sro[tid / 9][tid % 9] = ro[(cb + tid / 9) * 9 + tid % 9];
    __syncthreads();

    int p = blockIdx.x * 128 + tid;
    int r = p / Ww, q = p - r * Ww;
    float v = (float)((r + 1) * Wp + (q + 1));
    float o = 3.f / (1.f + expf(-xr[p]));
    const float PM1 = (float)(Pp - 1);

    if (blockIdx.x >= 3 && blockIdx.x <= 92) {
        // -------- fast path: rows 2..61 guaranteed, clamp provably inactive --
        int   base[6];
        float Wt[6][3];
#pragma unroll
        for (int t = 0; t < 6; t++) {
            int dy = (t >> 1) - 1;          // -1,0,1
            int sx = t & 1;                 // 0: xo=-1, 1: xo=+1
            float xo = sx ? 1.f : -1.f;
            float d  = (float)(dy * Wp);
            float pre   = v + xo + d;
            float offv  = __fadd_rn(__fmul_rn(o, xo), d);
            float after = pre + offv;
            float fo = floorf(offv), co = ceilf(offv);
            float avf  = pre + fo;
            float avf1 = avf + xo;
            float avc  = pre + co;
            float avc1 = avc + xo;
            float a1 = fabsf((after - avf)  / (float)Wp);
            float a2 = fabsf((avc1 - after) / (float)Wp);
            float w0 = a1 * fabsf(after - avf);
            float w1 = a1 * fabsf(avf1 - after);
            float w2 = a2 * fabsf(avc - after);
            float w3 = a2 * fabsf(after - avc1);
            bool ii = (co == fo);           // integer offset (rare)
            if (sx) {                       // xo=+1: positions i0, i0+1, i0+2
                base[t] = (int)avf;
                Wt[t][0] = w0 + (ii ? w2 : 0.f);
                Wt[t][1] = w1 + (ii ? w3 : w2);
                Wt[t][2] = ii ? 0.f : w3;
            } else {                        // xo=-1: positions i0-1, i0, i0+1
                base[t] = (int)avf - 1;
                Wt[t][0] = w1 + (ii ? w3 : 0.f);
                Wt[t][1] = w0 + (ii ? w2 : w3);
                Wt[t][2] = ii ? 0.f : w2;
            }
        }
#pragma unroll
        for (int j = 0; j < 8; j++) {
            const float* xp = g_xpad + (size_t)(cb + j) * Pp;
            float acc = 0.f;
#pragma unroll
            for (int t = 0; t < 6; t++) {
                int k = (t >> 1) * 3 + ((t & 1) ? 2 : 0);
                const float* bp = xp + base[t];
                float s = Wt[t][0] * __ldg(bp)
                        + Wt[t][1] * __ldg(bp + 1)
                        + Wt[t][2] * __ldg(bp + 2);
                acc += sro[j][k] * s;
            }
            g_Y[(size_t)(cb + j) * HW + p] = acc;
        }
    } else {
        // -------- generic path (edge rows; exact R2 code) --------------------
        int   idx[9][4];
        float wgt[9][4];
#pragma unroll
        for (int k = 0; k < 9; k++) {
            float xo = (float)(k % 3 - 1);
            float d  = (float)((k / 3 - 1) * Wp);
            float pre   = v + xo + d;
            float offv  = __fadd_rn(__fmul_rn(o, xo), d);
            float after = pre + offv;
            float fo = floorf(offv), co = ceilf(offv);
            float avf  = fminf(fmaxf(pre + fo, 0.f), PM1);
            float avf1 = fminf(fmaxf(avf + xo, 0.f), PM1);
            float avc  = fminf(fmaxf(pre + co, 0.f), PM1);
            float avc1 = fminf(fmaxf(avc + xo, 0.f), PM1);
            float a1 = fabsf((after - avf)  / (float)Wp);
            float a2 = fabsf((avc1 - after) / (float)Wp);
            wgt[k][0] = a1 * fabsf(after - avf);
            wgt[k][1] = a1 * fabsf(avf1 - after);
            wgt[k][2] = a2 * fabsf(avc - after);
            wgt[k][3] = a2 * fabsf(after - avc1);
            idx[k][0] = (int)avf;  idx[k][1] = (int)avf1;
            idx[k][2] = (int)avc;  idx[k][3] = (int)avc1;
        }
#pragma unroll
        for (int j = 0; j < 8; j++) {
            const float* xp = g_xpad + (size_t)(cb + j) * Pp;
            float acc = 0.f;
#pragma unroll
            for (int k = 0; k < 9; k++) {
                float s = wgt[k][0] * __ldg(xp + idx[k][0])
                        + wgt[k][1] * __ldg(xp + idx[k][1])
                        + wgt[k][2] * __ldg(xp + idx[k][2])
                        + wgt[k][3] * __ldg(xp + idx[k][3]);
                acc += sro[j][k] * s;
            }
            g_Y[(size_t)(cb + j) * HW + p] = acc;
        }
    }
}

// ---------------- f32x2 GEMM (NN): Z[o,p] = sum_k A[o,k]*B[k][p] ------------
// tile 64o x 64p, 128 threads, microtile 8o x 4p, FFMA2 inner loop.
// Epilogue: writes Z and per-(channel, p-block) partial sum / sumsq.
__global__ __launch_bounds__(128) void k_gemm(const float* __restrict__ A,
                                              const float* __restrict__ B,
                                              float* __restrict__ Z, int K) {
    __shared__ float2 As2[16][64];
    __shared__ float  Bs[16][64];
    int bx = blockIdx.x, by = blockIdx.y;
    int pbase = bx * 64, obase = by * 64;
    int tid = threadIdx.x;
    int og = tid >> 4, pg = tid & 15;
    unsigned long long acc[8][2] = {};

    for (int kc = 0; kc < K; kc += 16) {
#pragma unroll
        for (int i = 0; i < 2; i++) {
            int quad = tid + i * 128;
            int oo = quad >> 2, kq = (quad & 3) * 4;
            float4 a = *(const float4*)(A + (obase + oo) * K + kc + kq);
            As2[kq + 0][oo] = make_float2(a.x, a.x);
            As2[kq + 1][oo] = make_float2(a.y, a.y);
            As2[kq + 2][oo] = make_float2(a.z, a.z);
            As2[kq + 3][oo] = make_float2(a.w, a.w);
        }
#pragma unroll
        for (int i = 0; i < 2; i++) {
            int quad = tid + i * 128;
            int kk = quad >> 4, pq = (quad & 15) * 4;
            *(float4*)&Bs[kk][pq] =
                *(const float4*)(B + (size_t)(kc + kk) * HW + pbase + pq);
        }
        __syncthreads();
#pragma unroll
        for (int kk = 0; kk < 16; kk++) {
            ulonglong2 b2 = *(const ulonglong2*)&Bs[kk][pg * 4];
#pragma unroll
            for (int i2 = 0; i2 < 4; i2++) {
                ulonglong2 a2 = *(const ulonglong2*)&As2[kk][og * 8 + i2 * 2];
                FFMA2(acc[i2 * 2 + 0][0], a2.x, b2.x);
                FFMA2(acc[i2 * 2 + 0][1], a2.x, b2.y);
                FFMA2(acc[i2 * 2 + 1][0], a2.y, b2.x);
                FFMA2(acc[i2 * 2 + 1][1], a2.y, b2.y);
            }
        }
        __syncthreads();
    }

    float s[8], qq[8];
#pragma unroll
    for (int i = 0; i < 8; i++) {
        float2 lo = *(float2*)&acc[i][0];
        float2 hi = *(float2*)&acc[i][1];
        *(float4*)(Z + (size_t)(obase + og * 8 + i) * HW + pbase + pg * 4) =
            make_float4(lo.x, lo.y, hi.x, hi.y);
        s[i]  = lo.x + lo.y + hi.x + hi.y;
        qq[i] = lo.x * lo.x + lo.y * lo.y + hi.x * hi.x + hi.y * hi.y;
    }
#pragma unroll
    for (int i = 0; i < 8; i++) {
#pragma unroll
        for (int w = 8; w; w >>= 1) {
            s[i]  += __shfl_down_sync(0xffffffff, s[i],  w, 16);
            qq[i] += __shfl_down_sync(0xffffffff, qq[i], w, 16);
        }
    }
    if (pg == 0) {
#pragma unroll
        for (int i = 0; i < 8; i++) {
            g_ps[(obase + og * 8 + i) * NPB + bx] = s[i];
            g_pq[(obase + og * 8 + i) * NPB + bx] = qq[i];
        }
    }
}

// ---------------- finish BN stats -> scale/shift -----------------------------
__global__ void k_stats2(const float* __restrict__ g, const float* __restrict__ b) {
    __shared__ float ss[256], sq[256];
    int c = blockIdx.x, t = threadIdx.x;
    float s = 0.f, q = 0.f;
    if (t < NPB) { s = g_ps[c * NPB + t]; q = g_pq[c * NPB + t]; }
    ss[t] = s; sq[t] = q;
    __syncthreads();
    for (int st = 128; st; st >>= 1) {
        if (t < st) { ss[t] += ss[t + st]; sq[t] += sq[t + st]; }
        __syncthreads();
    }
    if (t == 0) {
        float mu  = ss[0] / (float)HW;
        float var = sq[0] / (float)HW - mu * mu;
        float rs  = rsqrtf(var + EPSV);
        float sc  = g[c] * rs;
        g_sc[c] = sc;
        g_sh[c] = b[c] - mu * sc;
    }
}

// ---------------- depthwise 3x3 on act(Z) -----------------------------------
__global__ void k_dw(const float* __restrict__ Z, const float* __restrict__ dwz,
                     float* __restrict__ T) {
    int c = blockIdx.y;
    int p = blockIdx.x * 256 + threadIdx.x;
    int r = p / Ww, q = p - r * Ww;
    float sc = g_sc[c], sh = g_sh[c];
    const float* z = Z + (size_t)c * HW;
    float acc = 0.f;
#pragma unroll
    for (int ky = 0; ky < 3; ky++) {
#pragma unroll
        for (int kx = 0; kx < 3; kx++) {
            int rr = r + ky - 1, qc = q + kx - 1;
            if (rr >= 0 && rr < Hh && qc >= 0 && qc < Ww) {
                float val = z[rr * Ww + qc] * sc + sh;
                val = (val >= 0.f) ? val : LEAK * val;
                acc += dwz[c * 9 + ky * 3 + kx] * val;
            }
        }
    }
    T[(size_t)c * HW + p] = acc;
}

// ---------------- final BN+leaky apply ---------------------------------------
__global__ void k_apply(const float* __restrict__ Z, float* __restrict__ out) {
    int i = blockIdx.x * 256 + threadIdx.x;
    int c = i / HW;
    float v = Z[i] * g_sc[c] + g_sh[c];
    out[i] = (v >= 0.f) ? v : LEAK * v;
}

// ---------------- launch ------------------------------------------------------
extern "C" void kernel_launch(void* const* d_in, const int* in_sizes, int n_in,
                              void* d_out, int out_size) {
    const float* x   = (const float*)d_in[0];
    const float* xr  = (const float*)d_in[1];
    const float* ro  = (const float*)d_in[2];
    const float* wr  = (const float*)d_in[3];
    const float* gr  = (const float*)d_in[4];
    const float* br  = (const float*)d_in[5];
    const float* dw1 = (const float*)d_in[6];
    const float* pw1 = (const float*)d_in[7];
    const float* g1  = (const float*)d_in[8];
    const float* b1  = (const float*)d_in[9];
    const float* dw2 = (const float*)d_in[10];
    const float* pw2 = (const float*)d_in[11];
    const float* g2  = (const float*)d_in[12];
    const float* b2  = (const float*)d_in[13];
    float* out = (float*)d_out;

    float *pY, *pZ, *pT;
    cudaGetSymbolAddress((void**)&pY, g_Y);
    cudaGetSymbolAddress((void**)&pZ, g_Z);
    cudaGetSymbolAddress((void**)&pT, g_T);

    k_pad<<<(CIN * Pp + 255) / 256, 256>>>(x);
    k_gather<<<dim3(HW / 128, CIN / 8), 128>>>(xr, ro);

    k_gemm<<<dim3(NPB, 2), 128>>>(wr, pY, pZ, CIN);
    k_stats2<<<COUT, 256>>>(gr, br);

    k_dw<<<dim3(HW / 256, COUT), 256>>>(pZ, dw1, pT);
    k_gemm<<<dim3(NPB, 2), 128>>>(pw1, pT, pZ, COUT);
    k_stats2<<<COUT, 256>>>(g1, b1);

    k_dw<<<dim3(HW / 256, COUT), 256>>>(pZ, dw2, pT);
    k_gemm<<<dim3(NPB, 2), 128>>>(pw2, pT, pZ, COUT);
    k_stats2<<<COUT, 256>>>(g2, b2);

    k_apply<<<(COUT * HW) / 256, 256>>>(pZ, out);
}